// round 1
// baseline (speedup 1.0000x reference)
#include <cuda_runtime.h>
#include <math.h>

// Problem constants (from reference)
#define L_A        128
#define B_DIM      64
#define NUM_PAIRS  (L_A * B_DIM)   // 8192
#define NUM_RULES  256
#define NUM_TOKENS 32000
#define MAX_QUERY  512
#define EPS_VAL    1e-7f

#define BLOCKS   32
#define THREADS  256   // BLOCKS * THREADS == NUM_PAIRS

__device__ float g_partials[BLOCKS];

__device__ __forceinline__ float gather_or_zero(const float* __restrict__ p,
                                                int pair, int stride, int idx) {
    // idx == -1 contributes 0 (matches reference _gather_prob)
    int safe = idx < 0 ? 0 : idx;
    float v = __ldg(p + (long long)pair * stride + safe);
    return (idx == -1) ? 0.0f : v;
}

__global__ void loss_gather_kernel(const float* __restrict__ rule_prob,
                                   const float* __restrict__ token_prob,
                                   const float* __restrict__ copy_prob,
                                   const int*   __restrict__ gt_rule,
                                   const int*   __restrict__ gt_token,
                                   const int*   __restrict__ gt_copy,
                                   const float* __restrict__ mask) {
    int pair = blockIdx.x * blockDim.x + threadIdx.x;   // 0..8191

    // Load indices first (independent), then issue all 3 gathers (independent → MLP=3+)
    int r = gt_rule[pair];
    int t = gt_token[pair];
    int c = gt_copy[pair];
    float m = mask[pair];

    float prob = gather_or_zero(rule_prob,  pair, NUM_RULES,  r)
               + gather_or_zero(token_prob, pair, NUM_TOKENS, t)
               + gather_or_zero(copy_prob,  pair, MAX_QUERY,  c);

    // reference: prob = prob + (prob < EPS) * EPS   (an add, not a clamp)
    if (prob < EPS_VAL) prob += EPS_VAL;

    float loss = -logf(prob) * m;

    // --- block reduction: warp shuffle + shared ---
    #pragma unroll
    for (int off = 16; off > 0; off >>= 1)
        loss += __shfl_xor_sync(0xFFFFFFFFu, loss, off);

    __shared__ float warp_sums[THREADS / 32];
    int lane = threadIdx.x & 31;
    int wid  = threadIdx.x >> 5;
    if (lane == 0) warp_sums[wid] = loss;
    __syncthreads();

    if (wid == 0) {
        float v = (lane < THREADS / 32) ? warp_sums[lane] : 0.0f;
        #pragma unroll
        for (int off = 16; off > 0; off >>= 1)
            v += __shfl_xor_sync(0xFFFFFFFFu, v, off);
        if (lane == 0) g_partials[blockIdx.x] = v;
    }
}

__global__ void loss_final_kernel(float* __restrict__ out) {
    int lane = threadIdx.x;   // 32 threads
    float v = (lane < BLOCKS) ? g_partials[lane] : 0.0f;
    #pragma unroll
    for (int off = 16; off > 0; off >>= 1)
        v += __shfl_xor_sync(0xFFFFFFFFu, v, off);
    if (lane == 0) out[0] = v * (1.0f / (float)B_DIM);
}

extern "C" void kernel_launch(void* const* d_in, const int* in_sizes, int n_in,
                              void* d_out, int out_size) {
    const float* rule_prob  = (const float*)d_in[0];
    const float* token_prob = (const float*)d_in[1];
    const float* copy_prob  = (const float*)d_in[2];
    const int*   gt_rule    = (const int*)  d_in[3];
    const int*   gt_token   = (const int*)  d_in[4];
    const int*   gt_copy    = (const int*)  d_in[5];
    const float* mask       = (const float*)d_in[6];
    float* out = (float*)d_out;

    loss_gather_kernel<<<BLOCKS, THREADS>>>(rule_prob, token_prob, copy_prob,
                                            gt_rule, gt_token, gt_copy, mask);
    loss_final_kernel<<<1, 32>>>(out);
}